// round 8
// baseline (speedup 1.0000x reference)
#include <cuda_runtime.h>

// MPSLayer, single fused kernel (one graph node):
//   out[b,:] = (prod_t x[b,t]) * w + bias,   w = 1^T * (A_0...A_{D-1}) * P
// blocks [0,nprod):       matrix-chain tree -> g_w, then publish flag
// blocks [nprod, +NR):    per-row product (HBM stream), wait flag (~free,
//                         chain finishes ~4us, rows finish ~14us), write out.
// Last stream block resets sync words for the next graph replay.

#define R   16
#define RR  256
#define TS  20
#define CHUNK 16
#define MAXG  16
// g_sync layout: [0..MAXG-1] group counters, [MAXG] lvl2 counter,
//                [MAXG+1] w-ready flag, [MAXG+2] consumer-done counter
#define SYNC_LVL2 (MAXG)
#define SYNC_FLAG (MAXG + 1)
#define SYNC_DONE (MAXG + 2)

__device__ float g_part1[256 * RR];
__device__ float g_part2[MAXG * RR];
__device__ float g_w[4096];
__device__ int   g_sync[MAXG + 3];

struct ChainSm {
    float S[CHUNK - 1][R * TS];
    float M[2][RR];
    float u[R];
    int   rank;
};

// Ordered product of n (<=16) RxR matrices at base; result in sm->M[ret].
__device__ __forceinline__ int chain_prod(const float* __restrict__ base, int n,
                                          ChainSm* sm, int t, int i, int j) {
    __syncthreads();
    for (int s = 1; s < n; ++s)
        sm->S[s - 1][(t & 15) * TS + (t >> 4)] = base[(size_t)s * RR + t];
    sm->M[0][t] = base[t];
    __syncthreads();
    int cur = 0;
    for (int s = 1; s < n; ++s) {
        const float4* mrow = (const float4*)&sm->M[cur][i * R];
        const float4* bcol = (const float4*)&sm->S[s - 1][j * TS];
        float4 a0 = mrow[0], a1 = mrow[1], a2 = mrow[2], a3 = mrow[3];
        float4 b0 = bcol[0], b1 = bcol[1], b2 = bcol[2], b3 = bcol[3];
        float acc = a0.x * b0.x;
        acc = fmaf(a0.y, b0.y, acc); acc = fmaf(a0.z, b0.z, acc); acc = fmaf(a0.w, b0.w, acc);
        acc = fmaf(a1.x, b1.x, acc); acc = fmaf(a1.y, b1.y, acc);
        acc = fmaf(a1.z, b1.z, acc); acc = fmaf(a1.w, b1.w, acc);
        acc = fmaf(a2.x, b2.x, acc); acc = fmaf(a2.y, b2.y, acc);
        acc = fmaf(a2.z, b2.z, acc); acc = fmaf(a2.w, b2.w, acc);
        acc = fmaf(a3.x, b3.x, acc); acc = fmaf(a3.y, b3.y, acc);
        acc = fmaf(a3.z, b3.z, acc); acc = fmaf(a3.w, b3.w, acc);
        sm->M[cur ^ 1][t] = acc;
        cur ^= 1;
        __syncthreads();
    }
    return cur;
}

__global__ __launch_bounds__(256, 8)
void mps_fused(const float* __restrict__ x, const float* __restrict__ cores,
               const float* __restrict__ proj, const float* __restrict__ bias,
               float* __restrict__ out,
               int B, int D, int O, int nprod, int ngrp, int nconsumer) {
    const int t = threadIdx.x;

    if ((int)blockIdx.x < nprod) {
        // ---------------- chain producer path ----------------
        __shared__ ChainSm sm;
        const int i = t >> 4, j = t & 15;
        const int start = blockIdx.x * CHUNK;
        const int n = min(CHUNK, D - start);
        int cur = chain_prod(cores + (size_t)start * RR, n, &sm, t, i, j);
        g_part1[(size_t)blockIdx.x * RR + t] = sm.M[cur][t];
        __threadfence();
        const int grp = blockIdx.x >> 4;
        const int gsz = min(16, nprod - (grp << 4));
        if (t == 0) sm.rank = atomicAdd(&g_sync[grp], 1);
        __syncthreads();
        if (sm.rank == gsz - 1) {
            __threadfence();
            cur = chain_prod(g_part1 + (size_t)(grp << 4) * RR, gsz, &sm, t, i, j);
            g_part2[(size_t)grp * RR + t] = sm.M[cur][t];
            __threadfence();
            if (t == 0) sm.rank = atomicAdd(&g_sync[SYNC_LVL2], 1);
            __syncthreads();
            if (sm.rank == ngrp - 1) {
                __threadfence();
                cur = chain_prod(g_part2, ngrp, &sm, t, i, j);
                if (t < R) {
                    float s = 0.0f;
#pragma unroll
                    for (int ii = 0; ii < R; ++ii) s += sm.M[cur][ii * R + t];
                    sm.u[t] = s;
                }
                __syncthreads();
                for (int o = t; o < O; o += 256) {
                    float s = 0.0f;
#pragma unroll
                    for (int k = 0; k < R; ++k)
                        s = fmaf(sm.u[k], proj[k * O + o], s);
                    g_w[o] = s;
                }
                // reset tree counters for next replay (all producers are done)
                if (t <= SYNC_LVL2) g_sync[t] = 0;
                __threadfence();
                __syncthreads();
                if (t == 0) atomicExch(&g_sync[SYNC_FLAG], 1);   // publish w
            }
        }
        return;
    }

    // ---------------- streaming path: one warp per row ----------------
    const int w = t >> 5, lane = t & 31;
    const int row = ((int)blockIdx.x - nprod) * 8 + w;
    float p = 1.0f;
    if (row < B) {
        const float* xr = x + (size_t)row * D;
        const float4* xr4 = (const float4*)xr;
        const int n4 = D >> 2;
#pragma unroll 8
        for (int idx = lane; idx < n4; idx += 32) {
            float4 v = xr4[idx];
            p *= v.x * v.y * v.z * v.w;
        }
        for (int idx = (n4 << 2) + lane; idx < D; idx += 32)
            p *= xr[idx];
#pragma unroll
        for (int o = 16; o; o >>= 1)
            p *= __shfl_xor_sync(0xffffffffu, p, o);
    }

    // wait for w (chain publishes ~4us; rows take ~14us -> normally zero wait)
    if (lane == 0) {
        volatile int* f = &g_sync[SYNC_FLAG];
        while (*f == 0) __nanosleep(64);
    }
    __syncwarp();
    __threadfence();

    if (row < B) {
        float* orow = out + (size_t)row * O;
        if ((O & 3) == 0) {
            const int O4 = O >> 2;
            for (int o4 = lane; o4 < O4; o4 += 32) {
                float4 w4 = __ldcg(&((const float4*)g_w)[o4]);
                float4 bs = ((const float4*)bias)[o4];
                float4 r;
                if (p == 0.0f) r = bs;
                else {
                    r.x = fmaf(p, w4.x, bs.x); r.y = fmaf(p, w4.y, bs.y);
                    r.z = fmaf(p, w4.z, bs.z); r.w = fmaf(p, w4.w, bs.w);
                }
                ((float4*)orow)[o4] = r;
            }
        } else {
            for (int o = lane; o < O; o += 32)
                orow[o] = (p == 0.0f) ? bias[o] : fmaf(p, __ldcg(&g_w[o]), bias[o]);
        }
    }

    // last stream block resets flag + done counter for the next graph replay
    __syncthreads();
    if (t == 0) {
        const int r = atomicAdd(&g_sync[SYNC_DONE], 1);
        if (r == nconsumer - 1) {
            g_sync[SYNC_DONE] = 0;
            __threadfence();
            atomicExch(&g_sync[SYNC_FLAG], 0);
        }
    }
}

extern "C" void kernel_launch(void* const* d_in, const int* in_sizes, int n_in,
                              void* d_out, int out_size) {
    const float* x     = (const float*)d_in[0];  // (B, D)
    const float* cores = (const float*)d_in[1];  // (D, 16, 16)
    const float* proj  = (const float*)d_in[2];  // (16, O)
    const float* bias  = (const float*)d_in[3];  // (O,)
    float* out = (float*)d_out;                  // (B, O)

    const int D = in_sizes[1] / RR;
    const int B = in_sizes[0] / D;
    const int O = in_sizes[3];

    int nprod = (D + CHUNK - 1) / CHUNK;         // 128 for D=2048
    if (nprod > 256) nprod = 256;
    const int ngrp = (nprod + 15) / 16;          // 8

    const int row_blocks = (B + 7) / 8;          // 1024
    mps_fused<<<nprod + row_blocks, 256>>>(x, cores, proj, bias, out,
                                           B, D, O, nprod, ngrp, row_blocks);
}

// round 9
// speedup vs baseline: 2.2047x; 2.2047x over previous
#include <cuda_runtime.h>

// MPSLayer, single fused kernel (one graph node):
//   out[b,:] = (prod_t x[b,t]) * w + bias,   w = 1^T * (A_0...A_{D-1}) * P
// blocks [0,nprod):    matrix-chain tree -> g_w, publish flag (own cache line)
// blocks [nprod,...):  per-row product (HBM stream), block-level backoff wait
//                      on flag (normally zero wait), write out directly.
// Sync words are one-per-128B-line so pollers never contend with elections.

#define R   16
#define RR  256
#define TS  20
#define CHUNK 16
#define MAXG  16
#define LINE  32   // ints per 128B line

__device__ float g_part1[256 * RR];
__device__ float g_part2[MAXG * RR];
__device__ float g_w[4096];
// each sync word on its own 128-byte line:
//   g_cnt[g*LINE]      : group counters g=0..MAXG-1
//   g_cnt[MAXG*LINE]   : level-2 counter
__device__ __align__(128) int g_cnt[(MAXG + 1) * LINE];
__device__ __align__(128) int g_flag[LINE];   // [0] = w ready
__device__ __align__(128) int g_done[LINE];   // [0] = consumer-done counter

struct ChainSm {
    float S[CHUNK - 1][R * TS];
    float M[2][RR];
    float u[R];
    int   rank;
};

// Ordered product of n (<=16) RxR matrices at base; result in sm->M[ret].
__device__ __forceinline__ int chain_prod(const float* __restrict__ base, int n,
                                          ChainSm* sm, int t, int i, int j) {
    __syncthreads();
    for (int s = 1; s < n; ++s)
        sm->S[s - 1][(t & 15) * TS + (t >> 4)] = base[(size_t)s * RR + t];
    sm->M[0][t] = base[t];
    __syncthreads();
    int cur = 0;
    for (int s = 1; s < n; ++s) {
        const float4* mrow = (const float4*)&sm->M[cur][i * R];
        const float4* bcol = (const float4*)&sm->S[s - 1][j * TS];
        float4 a0 = mrow[0], a1 = mrow[1], a2 = mrow[2], a3 = mrow[3];
        float4 b0 = bcol[0], b1 = bcol[1], b2 = bcol[2], b3 = bcol[3];
        float acc = a0.x * b0.x;
        acc = fmaf(a0.y, b0.y, acc); acc = fmaf(a0.z, b0.z, acc); acc = fmaf(a0.w, b0.w, acc);
        acc = fmaf(a1.x, b1.x, acc); acc = fmaf(a1.y, b1.y, acc);
        acc = fmaf(a1.z, b1.z, acc); acc = fmaf(a1.w, b1.w, acc);
        acc = fmaf(a2.x, b2.x, acc); acc = fmaf(a2.y, b2.y, acc);
        acc = fmaf(a2.z, b2.z, acc); acc = fmaf(a2.w, b2.w, acc);
        acc = fmaf(a3.x, b3.x, acc); acc = fmaf(a3.y, b3.y, acc);
        acc = fmaf(a3.z, b3.z, acc); acc = fmaf(a3.w, b3.w, acc);
        sm->M[cur ^ 1][t] = acc;
        cur ^= 1;
        __syncthreads();
    }
    return cur;
}

__global__ __launch_bounds__(256, 8)
void mps_fused(const float* __restrict__ x, const float* __restrict__ cores,
               const float* __restrict__ proj, const float* __restrict__ bias,
               float* __restrict__ out,
               int B, int D, int O, int nprod, int ngrp, int nconsumer) {
    const int t = threadIdx.x;

    if ((int)blockIdx.x < nprod) {
        // ---------------- chain producer path ----------------
        __shared__ ChainSm sm;
        const int i = t >> 4, j = t & 15;
        const int start = blockIdx.x * CHUNK;
        const int n = min(CHUNK, D - start);
        int cur = chain_prod(cores + (size_t)start * RR, n, &sm, t, i, j);
        g_part1[(size_t)blockIdx.x * RR + t] = sm.M[cur][t];
        __threadfence();
        const int grp = blockIdx.x >> 4;
        const int gsz = min(16, nprod - (grp << 4));
        if (t == 0) sm.rank = atomicAdd(&g_cnt[grp * LINE], 1);
        __syncthreads();
        if (sm.rank == gsz - 1) {
            __threadfence();
            cur = chain_prod(g_part1 + (size_t)(grp << 4) * RR, gsz, &sm, t, i, j);
            g_part2[(size_t)grp * RR + t] = sm.M[cur][t];
            __threadfence();
            if (t == 0) sm.rank = atomicAdd(&g_cnt[MAXG * LINE], 1);
            __syncthreads();
            if (sm.rank == ngrp - 1) {
                __threadfence();
                cur = chain_prod(g_part2, ngrp, &sm, t, i, j);
                if (t < R) {
                    float s = 0.0f;
#pragma unroll
                    for (int ii = 0; ii < R; ++ii) s += sm.M[cur][ii * R + t];
                    sm.u[t] = s;
                }
                __syncthreads();
                for (int o = t; o < O; o += 256) {
                    float s = 0.0f;
#pragma unroll
                    for (int k = 0; k < R; ++k)
                        s = fmaf(sm.u[k], proj[k * O + o], s);
                    g_w[o] = s;
                }
                // reset election counters for next replay (all producers done)
                if (t <= MAXG) g_cnt[t * LINE] = 0;
                __threadfence();
                __syncthreads();
                if (t == 0) atomicExch(&g_flag[0], 1);   // publish w
            }
        }
        return;
    }

    // ---------------- streaming path: one warp per row ----------------
    const int w = t >> 5, lane = t & 31;
    const int row = ((int)blockIdx.x - nprod) * 8 + w;
    float p = 1.0f;
    if (row < B) {
        const float* xr = x + (size_t)row * D;
        const float4* xr4 = (const float4*)xr;
        const int n4 = D >> 2;
#pragma unroll 8
        for (int idx = lane; idx < n4; idx += 32) {
            float4 v = xr4[idx];
            p *= v.x * v.y * v.z * v.w;
        }
        for (int idx = (n4 << 2) + lane; idx < D; idx += 32)
            p *= xr[idx];
#pragma unroll
        for (int o = 16; o; o >>= 1)
            p *= __shfl_xor_sync(0xffffffffu, p, o);
    }

    // block-level wait for w: 1 poller/block, exponential backoff.
    // chain publishes ~5us, rows finish ~14us -> normally zero iterations.
    if (t == 0) {
        volatile int* f = &g_flag[0];
        unsigned ns = 32;
        while (*f == 0) {
            __nanosleep(ns);
            if (ns < 4096) ns <<= 1;
        }
        __threadfence();
    }
    __syncthreads();

    if (row < B) {
        float* orow = out + (size_t)row * O;
        if ((O & 3) == 0) {
            const int O4 = O >> 2;
            for (int o4 = lane; o4 < O4; o4 += 32) {
                float4 w4 = __ldcg(&((const float4*)g_w)[o4]);
                float4 bs = ((const float4*)bias)[o4];
                float4 r;
                if (p == 0.0f) r = bs;
                else {
                    r.x = fmaf(p, w4.x, bs.x); r.y = fmaf(p, w4.y, bs.y);
                    r.z = fmaf(p, w4.z, bs.z); r.w = fmaf(p, w4.w, bs.w);
                }
                ((float4*)orow)[o4] = r;
            }
        } else {
            for (int o = lane; o < O; o += 32)
                orow[o] = (p == 0.0f) ? bias[o] : fmaf(p, __ldcg(&g_w[o]), bias[o]);
        }
    }

    // last consumer block resets flag + done counter for the next replay
    __syncthreads();
    if (t == 0) {
        const int r = atomicAdd(&g_done[0], 1);
        if (r == nconsumer - 1) {
            g_done[0] = 0;
            __threadfence();
            atomicExch(&g_flag[0], 0);
        }
    }
}

extern "C" void kernel_launch(void* const* d_in, const int* in_sizes, int n_in,
                              void* d_out, int out_size) {
    const float* x     = (const float*)d_in[0];  // (B, D)
    const float* cores = (const float*)d_in[1];  // (D, 16, 16)
    const float* proj  = (const float*)d_in[2];  // (16, O)
    const float* bias  = (const float*)d_in[3];  // (O,)
    float* out = (float*)d_out;                  // (B, O)

    const int D = in_sizes[1] / RR;
    const int B = in_sizes[0] / D;
    const int O = in_sizes[3];

    int nprod = (D + CHUNK - 1) / CHUNK;         // 128 for D=2048
    if (nprod > 256) nprod = 256;
    const int ngrp = (nprod + 15) / 16;          // 8

    const int row_blocks = (B + 7) / 8;          // 1024
    mps_fused<<<nprod + row_blocks, 256>>>(x, cores, proj, bias, out,
                                           B, D, O, nprod, ngrp, row_blocks);
}